// round 3
// baseline (speedup 1.0000x reference)
#include <cuda_runtime.h>
#include <math.h>
#include <float.h>

// Problem constants
#define Bv   8
#define Lv   4096
#define LP   4097          // L + 1 (bias token)
#define KDv  512
#define EDv  1024
#define Hv   8
#define DK   64            // KD / H
#define DV   128           // ED / H
#define BH   64            // B * H
#define KCHUNK   (LP * DK)          // floats per (b,h) key chunk in raw view
#define VCHUNK   (LP * DV)          // floats per (b,h) value chunk in raw view
#define KBATCH   (Lv * KDv)         // real key floats per batch
#define VBATCH   (Lv * EDv)         // real value floats per batch
#define NT   8                      // j-tiles for the AV kernel
#define TILE 513                    // ceil(4097 / 8)
#define NROWG 513                   // ceil(4097 / 8) 8-row groups per bh

// Scratch (allocation-free rule: __device__ globals)
__device__ float g_scores[BH * LP];           // ~1.05 MB raw scores
__device__ float g_partial[BH * NT * DV];     // 256 KB
__device__ float g_max[BH];
__device__ float g_sum[BH];

// ---------------------------------------------------------------------------
// Kernel 1: scores[bh, j] = dot64(Q[h], K[bh, j, :]) * w[h,j] + bias[h,j]
// One warp per GROUP of 8 rows (2KB contiguous): lanes 0-15 even rows,
// lanes 16-31 odd rows; 4 front-batched float4 loads per lane (MLP=4).
// ---------------------------------------------------------------------------
__global__ void k_scores(const float* __restrict__ keys,
                         const float* __restrict__ k_bias,
                         const float* __restrict__ query,
                         const float* __restrict__ sw,
                         const float* __restrict__ sb) {
    int gw   = (blockIdx.x * blockDim.x + threadIdx.x) >> 5;
    int lane = threadIdx.x & 31;
    if (gw >= BH * NROWG) return;
    int bh = gw / NROWG;
    int g  = gw - bh * NROWG;
    int b  = bh >> 3;
    int h  = bh & 7;

    int half = lane >> 4;          // even/odd member of each pair
    int li   = lane & 15;          // float4 slot within row (64 floats)
    int j0   = g * 8;

    float4 qv = *(const float4*)(query + h * DK + li * 4);

    float4 kv[4];
    #pragma unroll
    for (int i = 0; i < 4; i++) {
        int j  = j0 + 2 * i + half;
        int jc = min(j, LP - 1);
        int f  = h * KCHUNK + jc * DK + li * 4;
        const float* kp = (f >= KBATCH) ? (k_bias + (f - KBATCH))
                                        : (keys + b * KBATCH + f);
        kv[i] = __ldcs((const float4*)kp);
    }

    #pragma unroll
    for (int i = 0; i < 4; i++) {
        float s = kv[i].x * qv.x + kv[i].y * qv.y + kv[i].z * qv.z + kv[i].w * qv.w;
        #pragma unroll
        for (int o = 8; o > 0; o >>= 1)
            s += __shfl_xor_sync(0xffffffffu, s, o);
        int j = j0 + 2 * i + half;
        if (li == 0 && j < LP) {
            int wi = h * LP + j;
            g_scores[bh * LP + j] = s * __ldg(sw + wi) + __ldg(sb + wi);
        }
    }
}

// ---------------------------------------------------------------------------
// Kernel 2: per-row stats only: m[bh] = max_j s, S[bh] = sum_j exp(s - m).
// No write-back of probabilities (k_av recomputes exp on the fly).
// ---------------------------------------------------------------------------
__device__ __forceinline__ float block_reduce(float v, float* sh, bool do_max) {
    int lane = threadIdx.x & 31, warp = threadIdx.x >> 5;
    #pragma unroll
    for (int o = 16; o > 0; o >>= 1) {
        float t = __shfl_xor_sync(0xffffffffu, v, o);
        v = do_max ? fmaxf(v, t) : (v + t);
    }
    if (lane == 0) sh[warp] = v;
    __syncthreads();
    int nw = blockDim.x >> 5;
    if (warp == 0) {
        v = (lane < nw) ? sh[lane] : (do_max ? -FLT_MAX : 0.0f);
        #pragma unroll
        for (int o = 16; o > 0; o >>= 1) {
            float t = __shfl_xor_sync(0xffffffffu, v, o);
            v = do_max ? fmaxf(v, t) : (v + t);
        }
        if (lane == 0) sh[0] = v;
    }
    __syncthreads();
    v = sh[0];
    __syncthreads();
    return v;
}

__global__ void k_stats() {
    __shared__ float sh[32];
    const float* row = g_scores + blockIdx.x * LP;

    float v[9];
    float m = -FLT_MAX;
    #pragma unroll
    for (int k = 0; k < 9; k++) {
        int j = threadIdx.x + k * 512;
        v[k] = (j < LP) ? row[j] : -FLT_MAX;
        m = fmaxf(m, v[k]);
    }
    m = block_reduce(m, sh, true);

    float s = 0.0f;
    #pragma unroll
    for (int k = 0; k < 9; k++) {
        int j = threadIdx.x + k * 512;
        if (j < LP) s += expf(v[k] - m);
    }
    s = block_reduce(s, sh, false);

    if (threadIdx.x == 0) {
        g_max[blockIdx.x] = m;
        g_sum[blockIdx.x] = s;
    }
}

// ---------------------------------------------------------------------------
// Kernel 3: partial[bh, tile, d] = sum_{j in tile} exp(s[bh,j]-m[bh]) * V[bh,j,d]
// grid = (NT, BH), 256 threads = 8 warps; warps interleave rows mod 8.
// ---------------------------------------------------------------------------
__global__ void k_av(const float* __restrict__ values,
                     const float* __restrict__ v_bias) {
    int tile = blockIdx.x;
    int bh   = blockIdx.y;
    int b = bh >> 3, h = bh & 7;
    int r8 = threadIdx.x >> 5;
    int c  = threadIdx.x & 31;

    const float* p = g_scores + bh * LP;
    float m = g_max[bh];
    int j0 = tile * TILE;
    int j1 = min(j0 + TILE, LP);

    float4 acc = make_float4(0.f, 0.f, 0.f, 0.f);
    #pragma unroll 4
    for (int j = j0 + r8; j < j1; j += 8) {
        float pj = expf(__ldg(p + j) - m);
        int f = h * VCHUNK + j * DV;
        const float* vrow = (f >= VBATCH) ? (v_bias + (f - VBATCH))
                                          : (values + b * VBATCH + f);
        float4 vv = __ldcs((const float4*)(vrow + c * 4));
        acc.x += pj * vv.x;
        acc.y += pj * vv.y;
        acc.z += pj * vv.z;
        acc.w += pj * vv.w;
    }

    __shared__ float4 red[8][32];
    red[r8][c] = acc;
    __syncthreads();
    if (r8 == 0) {
        float4 a = red[0][c];
        #pragma unroll
        for (int w = 1; w < 8; w++) {
            float4 x = red[w][c];
            a.x += x.x; a.y += x.y; a.z += x.z; a.w += x.w;
        }
        *(float4*)(g_partial + (bh * NT + tile) * DV + c * 4) = a;
    }
}

// ---------------------------------------------------------------------------
// Kernel 4: reduce NT partials (float4, MLP=8), divide by S, LayerNorm.
// One block of 256 threads per batch; each thread owns 4 consecutive dims.
// ---------------------------------------------------------------------------
__global__ void k_ln(const float* __restrict__ gamma,
                     const float* __restrict__ beta,
                     float* __restrict__ out) {
    __shared__ float sh_s[8];
    __shared__ float sh_q[8];
    int b = blockIdx.x;
    int t = threadIdx.x;            // 0..255
    int D = t * 4;                  // global embed index of first owned dim
    int h = t >> 5;                 // 128 dims per head / 4 = 32 threads per head
    int dd = D & 127;
    int bh = b * 8 + h;

    const float* pp = g_partial + bh * (NT * DV) + dd;
    float4 a = make_float4(0.f, 0.f, 0.f, 0.f);
    #pragma unroll
    for (int k = 0; k < NT; k++) {
        float4 x = *(const float4*)(pp + k * DV);
        a.x += x.x; a.y += x.y; a.z += x.z; a.w += x.w;
    }
    float invS = 1.0f / g_sum[bh];
    a.x *= invS; a.y *= invS; a.z *= invS; a.w *= invS;

    float s = a.x + a.y + a.z + a.w;
    float q = a.x * a.x + a.y * a.y + a.z * a.z + a.w * a.w;
    int lane = t & 31, warp = t >> 5;
    #pragma unroll
    for (int o = 16; o > 0; o >>= 1) {
        s += __shfl_xor_sync(0xffffffffu, s, o);
        q += __shfl_xor_sync(0xffffffffu, q, o);
    }
    if (lane == 0) { sh_s[warp] = s; sh_q[warp] = q; }
    __syncthreads();
    if (warp == 0 && lane < 8) {
        s = sh_s[lane];
        q = sh_q[lane];
        #pragma unroll
        for (int o = 4; o > 0; o >>= 1) {
            s += __shfl_xor_sync(0x000000ffu, s, o);
            q += __shfl_xor_sync(0x000000ffu, q, o);
        }
        if (lane == 0) { sh_s[0] = s; sh_q[0] = q; }
    }
    __syncthreads();
    float mean = sh_s[0] * (1.0f / EDv);
    float var  = sh_q[0] * (1.0f / EDv) - mean * mean;
    float inv  = rsqrtf(var + 1e-5f);

    float4 gm = *(const float4*)(gamma + D);
    float4 bt = *(const float4*)(beta + D);
    float4 o4;
    o4.x = (a.x - mean) * inv * gm.x + bt.x;
    o4.y = (a.y - mean) * inv * gm.y + bt.y;
    o4.z = (a.z - mean) * inv * gm.z + bt.z;
    o4.w = (a.w - mean) * inv * gm.w + bt.w;
    *(float4*)(out + b * EDv + D) = o4;
}

// ---------------------------------------------------------------------------
// Launch: inputs in metadata order:
// keys, values, query, k_bias, v_bias, softmax_weight, softmax_bias, gamma, beta
// ---------------------------------------------------------------------------
extern "C" void kernel_launch(void* const* d_in, const int* in_sizes, int n_in,
                              void* d_out, int out_size) {
    const float* keys   = (const float*)d_in[0];
    const float* values = (const float*)d_in[1];
    const float* query  = (const float*)d_in[2];
    const float* k_bias = (const float*)d_in[3];
    const float* v_bias = (const float*)d_in[4];
    const float* sw     = (const float*)d_in[5];
    const float* sb     = (const float*)d_in[6];
    const float* gamma  = (const float*)d_in[7];
    const float* beta   = (const float*)d_in[8];
    float* out = (float*)d_out;

    // K1: one warp per 8-row group; 256 threads = 8 warps per block
    int nwarps = BH * NROWG;               // 32832
    int blocks1 = (nwarps + 7) / 8;
    k_scores<<<blocks1, 256>>>(keys, k_bias, query, sw, sb);

    // K2: row stats (max, sumexp)
    k_stats<<<BH, 512>>>();

    // K3: attn @ V partials (unnormalized)
    dim3 g3(NT, BH);
    k_av<<<g3, 256>>>(values, v_bias);

    // K4: reduce + normalize + layernorm
    k_ln<<<Bv, 256>>>(gamma, beta, out);
}